// round 7
// baseline (speedup 1.0000x reference)
#include <cuda_runtime.h>
#include <cuda_fp16.h>

#define NUSER 100000
#define NITEM 50000
#define NEDGE 2000000
#define DIM   64
#define NLAYERS 3

// ---------------- scratch (device globals) ----------------
// fp16 operand buffers per layer: O_l = d^-1 * S_{l-1} (O_0 = d^-1/2 * emb)
__device__ __half g_ou0[NUSER * DIM];
__device__ __half g_ou1[NUSER * DIM];
__device__ __half g_ou2[NUSER * DIM];
__device__ __half g_cu [NUSER * DIM];   // last-layer contribution d^-1/2 * S_2
__device__ __half g_oi0[NITEM * DIM];
__device__ __half g_oi1[NITEM * DIM];
__device__ __half g_oi2[NITEM * DIM];
__device__ __half g_ci [NITEM * DIM];
__device__ __half g_au[NUSER * DIM];    // phase-A out, user rows (d_u^-1 * R(Oi))
__device__ __half g_ai[NITEM * DIM];    // phase-A out, item rows (d_i^-1 * RT(Ou))
__device__ int    g_cnt_u[NUSER];
__device__ int    g_cnt_i[NITEM];
__device__ int    g_rowptr_u[NUSER + 1];
__device__ int    g_rowptr_i[NITEM + 1];
__device__ int    g_cur_u[NUSER];
__device__ int    g_cur_i[NITEM];
__device__ int    g_cols_u[NEDGE];
__device__ int    g_cols_i[NEDGE];
__device__ float  g_nu_inv[NUSER];      // 1/d
__device__ float  g_nu_is [NUSER];      // d^-1/2
__device__ float  g_nu_sq [NUSER];      // d^+1/2
__device__ float  g_ni_inv[NITEM];
__device__ float  g_ni_is [NITEM];
__device__ float  g_ni_sq [NITEM];

// ---------------- helpers ----------------
__device__ __forceinline__ uint2 pack4h(float4 v) {
    __half2 a = __floats2half2_rn(v.x, v.y);
    __half2 b = __floats2half2_rn(v.z, v.w);
    uint2 r;
    r.x = *reinterpret_cast<unsigned*>(&a);
    r.y = *reinterpret_cast<unsigned*>(&b);
    return r;
}

__device__ __forceinline__ float4 unpack4h(uint2 v) {
    __half2 h0 = *reinterpret_cast<__half2*>(&v.x);
    __half2 h1 = *reinterpret_cast<__half2*>(&v.y);
    float2 f0 = __half22float2(h0);
    float2 f1 = __half22float2(h1);
    return make_float4(f0.x, f0.y, f1.x, f1.y);
}

// gather-add over one CSR row: 16 lanes per row, 8B (4 halves) per lane.
// fp32 accumulation. Moderate unroll (MLP_p1 ~ 4: avoids the cross-CTA
// L1tex-queue spread that front-batched loads trigger on B300).
__device__ __forceinline__ float4 gather_row(const uint2* __restrict__ src,
                                             const int*   __restrict__ cols,
                                             int beg, int end, int c, unsigned hmask) {
    float4 acc = make_float4(0.f, 0.f, 0.f, 0.f);
    for (int base = beg; base < end; base += 16) {
        int myi = base + c;
        int mycol = (myi < end) ? __ldg(cols + myi) : 0;
        int cnt = min(16, end - base);
        #pragma unroll 4
        for (int j = 0; j < cnt; ++j) {
            int col = __shfl_sync(hmask, mycol, j, 16);
            uint2 v = __ldg(src + col * 16 + c);
            float4 f = unpack4h(v);
            acc.x += f.x; acc.y += f.y; acc.z += f.z; acc.w += f.w;
        }
    }
    return acc;
}

// ---------------- CSR build ----------------
__global__ void hist_degrees(const int* __restrict__ u_idx,
                             const int* __restrict__ i_idx,
                             int* __restrict__ cnt_u, int* __restrict__ cnt_i) {
    int t = blockIdx.x * blockDim.x + threadIdx.x;
    if (t >= NEDGE) return;
    atomicAdd(cnt_u + __ldg(u_idx + t), 1);
    atomicAdd(cnt_i + __ldg(i_idx + t), 1);
}

// One kernel, 2 blocks of 1024: block 0 = users, block 1 = items.
__global__ void __launch_bounds__(1024)
fused_scan(const int* __restrict__ cnt_u, const int* __restrict__ cnt_i,
           int* __restrict__ rp_u, int* __restrict__ rp_i,
           int* __restrict__ cur_u, int* __restrict__ cur_i,
           float* __restrict__ nu_inv, float* __restrict__ nu_is, float* __restrict__ nu_sq,
           float* __restrict__ ni_inv, float* __restrict__ ni_is, float* __restrict__ ni_sq) {
    const bool users = (blockIdx.x == 0);
    const int n = users ? NUSER : NITEM;
    const int* __restrict__ cnt = users ? cnt_u : cnt_i;
    int* __restrict__ rp  = users ? rp_u  : rp_i;
    int* __restrict__ cur = users ? cur_u : cur_i;
    float* __restrict__ inv = users ? nu_inv : ni_inv;
    float* __restrict__ isq = users ? nu_is  : ni_is;
    float* __restrict__ sq  = users ? nu_sq  : ni_sq;

    const int per = (n + 1023) / 1024;
    int beg = threadIdx.x * per;
    int end = min(n, beg + per);

    int s = 0;
    for (int e = beg; e < end; ++e) s += __ldg(cnt + e);

    __shared__ int sh[1024];
    sh[threadIdx.x] = s;
    __syncthreads();
    for (int off = 1; off < 1024; off <<= 1) {
        int t = (threadIdx.x >= off) ? sh[threadIdx.x - off] : 0;
        __syncthreads();
        sh[threadIdx.x] += t;
        __syncthreads();
    }
    int run = sh[threadIdx.x] - s;   // exclusive prefix

    for (int e = beg; e < end; ++e) {
        int c = __ldg(cnt + e);
        rp[e]  = run;
        cur[e] = run;
        float d = c ? (float)c : 1.0f;
        inv[e] = 1.0f / d;
        isq[e] = rsqrtf(d);
        sq[e]  = sqrtf(d);
        run += c;
    }
    if (threadIdx.x == 0) rp[n] = NEDGE;
}

__global__ void fill_csr(const int* __restrict__ u_idx, const int* __restrict__ i_idx,
                         int* __restrict__ cur_u, int* __restrict__ cur_i,
                         int* __restrict__ cols_u, int* __restrict__ cols_i) {
    int e = blockIdx.x * blockDim.x + threadIdx.x;
    if (e >= NEDGE) return;
    int u = __ldg(u_idx + e);
    int i = __ldg(i_idx + e);
    cols_u[atomicAdd(cur_u + u, 1)] = i;
    cols_i[atomicAdd(cur_i + i, 1)] = u;
}

// ---------------- prescale: O_0 = d^-1/2 * emb  (fp32 -> fp16) ----------------
__global__ void prescale(const float4* __restrict__ ue, const float4* __restrict__ ie,
                         const float* __restrict__ nu_is, const float* __restrict__ ni_is,
                         uint2* __restrict__ ou, uint2* __restrict__ oi) {
    int t = blockIdx.x * blockDim.x + threadIdx.x;
    if (t >= (NUSER + NITEM) * 16) return;
    if (t < NUSER * 16) {
        float s = __ldg(nu_is + (t >> 4));
        float4 v = __ldg(ue + t);
        v.x *= s; v.y *= s; v.z *= s; v.w *= s;
        ou[t] = pack4h(v);
    } else {
        int tt = t - NUSER * 16;
        float s = __ldg(ni_is + (tt >> 4));
        float4 v = __ldg(ie + tt);
        v.x *= s; v.y *= s; v.z *= s; v.w *= s;
        oi[tt] = pack4h(v);
    }
}

// ---------------- phase A: ai = d_i^-1 * RT(Ou);  au = d_u^-1 * R(Oi) ----------------
__global__ void __launch_bounds__(256)
phaseA(const uint2* __restrict__ ou, const uint2* __restrict__ oi,
       const int* __restrict__ rp_i, const int* __restrict__ cols_i,
       const int* __restrict__ rp_u, const int* __restrict__ cols_u,
       const float* __restrict__ ni_inv, const float* __restrict__ nu_inv,
       uint2* __restrict__ ai, uint2* __restrict__ au) {
    int t = blockIdx.x * blockDim.x + threadIdx.x;
    int r = t >> 4;
    if (r >= NITEM + NUSER) return;
    int c = t & 15;
    unsigned hmask = 0xFFFFu << (threadIdx.x & 16);
    if (r < NITEM) {
        float4 acc = gather_row(ou, cols_i, __ldg(rp_i + r), __ldg(rp_i + r + 1), c, hmask);
        float s = __ldg(ni_inv + r);
        acc.x *= s; acc.y *= s; acc.z *= s; acc.w *= s;
        ai[r * 16 + c] = pack4h(acc);
    } else {
        int u = r - NITEM;
        float4 acc = gather_row(oi, cols_u, __ldg(rp_u + u), __ldg(rp_u + u + 1), c, hmask);
        float s = __ldg(nu_inv + u);
        acc.x *= s; acc.y *= s; acc.z *= s; acc.w *= s;
        au[u * 16 + c] = pack4h(acc);
    }
}

// ---------------- phase B: out_u = scl_u * R(ai);  out_i = scl_i * RT(au) ----------------
// scl = d^-1 for layers 0..n-2 (produces next operand O_{l+1}),
// scl = d^-1/2 for the last layer (produces contribution C).
__global__ void __launch_bounds__(256)
phaseB(const uint2* __restrict__ ai, const uint2* __restrict__ au,
       const int* __restrict__ rp_u, const int* __restrict__ cols_u,
       const int* __restrict__ rp_i, const int* __restrict__ cols_i,
       const float* __restrict__ scl_u, const float* __restrict__ scl_i,
       uint2* __restrict__ out_u, uint2* __restrict__ out_i) {
    int t = blockIdx.x * blockDim.x + threadIdx.x;
    int r = t >> 4;
    if (r >= NITEM + NUSER) return;
    int c = t & 15;
    unsigned hmask = 0xFFFFu << (threadIdx.x & 16);
    if (r < NUSER) {
        float4 S = gather_row(ai, cols_u, __ldg(rp_u + r), __ldg(rp_u + r + 1), c, hmask);
        float s = __ldg(scl_u + r);
        S.x *= s; S.y *= s; S.z *= s; S.w *= s;
        out_u[r * 16 + c] = pack4h(S);
    } else {
        int i = r - NUSER;
        float4 S = gather_row(au, cols_i, __ldg(rp_i + i), __ldg(rp_i + i + 1), c, hmask);
        float s = __ldg(scl_i + i);
        S.x *= s; S.y *= s; S.z *= s; S.w *= s;
        out_i[i * 16 + c] = pack4h(S);
    }
}

// ---------------- final: out = 0.25*(emb + d^1/2*(O1+O2) + C) ----------------
__global__ void final_sum(const float4* __restrict__ emb_u, const float4* __restrict__ emb_i,
                          const float* __restrict__ nu_sq, const float* __restrict__ ni_sq,
                          const uint2* __restrict__ ou1, const uint2* __restrict__ ou2,
                          const uint2* __restrict__ cu,
                          const uint2* __restrict__ oi1, const uint2* __restrict__ oi2,
                          const uint2* __restrict__ ci,
                          float4* __restrict__ out) {
    int t = blockIdx.x * blockDim.x + threadIdx.x;
    if (t >= (NUSER + NITEM) * 16) return;
    const float k = 1.0f / (NLAYERS + 1);
    float4 e, a, b, cc; float sq;
    if (t < NUSER * 16) {
        sq = __ldg(nu_sq + (t >> 4));
        e  = __ldg(emb_u + t);
        a  = unpack4h(__ldg(ou1 + t));
        b  = unpack4h(__ldg(ou2 + t));
        cc = unpack4h(__ldg(cu  + t));
    } else {
        int tt = t - NUSER * 16;
        sq = __ldg(ni_sq + (tt >> 4));
        e  = __ldg(emb_i + tt);
        a  = unpack4h(__ldg(oi1 + tt));
        b  = unpack4h(__ldg(oi2 + tt));
        cc = unpack4h(__ldg(ci  + tt));
    }
    float4 o;
    o.x = k * (e.x + sq * (a.x + b.x) + cc.x);
    o.y = k * (e.y + sq * (a.y + b.y) + cc.y);
    o.z = k * (e.z + sq * (a.z + b.z) + cc.z);
    o.w = k * (e.w + sq * (a.w + b.w) + cc.w);
    out[t] = o;
}

// ---------------- launch ----------------
extern "C" void kernel_launch(void* const* d_in, const int* in_sizes, int n_in,
                              void* d_out, int out_size) {
    const float* user_emb = (const float*)d_in[0];
    const float* item_emb = (const float*)d_in[1];
    const int*   u_idx    = (const int*)d_in[2];
    const int*   i_idx    = (const int*)d_in[3];
    float* out = (float*)d_out;

    __half *p_ou0, *p_ou1, *p_ou2, *p_cu, *p_oi0, *p_oi1, *p_oi2, *p_ci, *p_au, *p_ai;
    float *p_nu_inv, *p_nu_is, *p_nu_sq, *p_ni_inv, *p_ni_is, *p_ni_sq;
    int *p_cnt_u, *p_cnt_i, *p_rp_u, *p_rp_i, *p_cur_u, *p_cur_i, *p_cols_u, *p_cols_i;
    cudaGetSymbolAddress((void**)&p_ou0, g_ou0);
    cudaGetSymbolAddress((void**)&p_ou1, g_ou1);
    cudaGetSymbolAddress((void**)&p_ou2, g_ou2);
    cudaGetSymbolAddress((void**)&p_cu,  g_cu);
    cudaGetSymbolAddress((void**)&p_oi0, g_oi0);
    cudaGetSymbolAddress((void**)&p_oi1, g_oi1);
    cudaGetSymbolAddress((void**)&p_oi2, g_oi2);
    cudaGetSymbolAddress((void**)&p_ci,  g_ci);
    cudaGetSymbolAddress((void**)&p_au,  g_au);
    cudaGetSymbolAddress((void**)&p_ai,  g_ai);
    cudaGetSymbolAddress((void**)&p_nu_inv, g_nu_inv);
    cudaGetSymbolAddress((void**)&p_nu_is,  g_nu_is);
    cudaGetSymbolAddress((void**)&p_nu_sq,  g_nu_sq);
    cudaGetSymbolAddress((void**)&p_ni_inv, g_ni_inv);
    cudaGetSymbolAddress((void**)&p_ni_is,  g_ni_is);
    cudaGetSymbolAddress((void**)&p_ni_sq,  g_ni_sq);
    cudaGetSymbolAddress((void**)&p_cnt_u,  g_cnt_u);
    cudaGetSymbolAddress((void**)&p_cnt_i,  g_cnt_i);
    cudaGetSymbolAddress((void**)&p_rp_u,   g_rowptr_u);
    cudaGetSymbolAddress((void**)&p_rp_i,   g_rowptr_i);
    cudaGetSymbolAddress((void**)&p_cur_u,  g_cur_u);
    cudaGetSymbolAddress((void**)&p_cur_i,  g_cur_i);
    cudaGetSymbolAddress((void**)&p_cols_u, g_cols_u);
    cudaGetSymbolAddress((void**)&p_cols_i, g_cols_i);

    const int TB = 256;
    const int EDGE_BLKS = (NEDGE + TB - 1) / TB;
    const int ALL_BLKS  = ((NUSER + NITEM) * 16 + TB - 1) / TB;

    // ---- CSR build + norms (fused prologue) ----
    cudaMemsetAsync(p_cnt_u, 0, NUSER * sizeof(int), 0);
    cudaMemsetAsync(p_cnt_i, 0, NITEM * sizeof(int), 0);
    hist_degrees<<<EDGE_BLKS, TB>>>(u_idx, i_idx, p_cnt_u, p_cnt_i);
    fused_scan<<<2, 1024>>>(p_cnt_u, p_cnt_i, p_rp_u, p_rp_i, p_cur_u, p_cur_i,
                            p_nu_inv, p_nu_is, p_nu_sq, p_ni_inv, p_ni_is, p_ni_sq);
    fill_csr<<<EDGE_BLKS, TB>>>(u_idx, i_idx, p_cur_u, p_cur_i, p_cols_u, p_cols_i);

    // ---- initial operands O_0 ----
    prescale<<<ALL_BLKS, TB>>>((const float4*)user_emb, (const float4*)item_emb,
                               p_nu_is, p_ni_is, (uint2*)p_ou0, (uint2*)p_oi0);

    // ---- layers ----
    uint2* OU[3] = { (uint2*)p_ou0, (uint2*)p_ou1, (uint2*)p_ou2 };
    uint2* OI[3] = { (uint2*)p_oi0, (uint2*)p_oi1, (uint2*)p_oi2 };
    for (int layer = 0; layer < NLAYERS; ++layer) {
        phaseA<<<ALL_BLKS, TB>>>((const uint2*)OU[layer], (const uint2*)OI[layer],
                                 p_rp_i, p_cols_i, p_rp_u, p_cols_u,
                                 p_ni_inv, p_nu_inv, (uint2*)p_ai, (uint2*)p_au);
        if (layer < NLAYERS - 1) {
            phaseB<<<ALL_BLKS, TB>>>((const uint2*)p_ai, (const uint2*)p_au,
                                     p_rp_u, p_cols_u, p_rp_i, p_cols_i,
                                     p_nu_inv, p_ni_inv,
                                     OU[layer + 1], OI[layer + 1]);
        } else {
            phaseB<<<ALL_BLKS, TB>>>((const uint2*)p_ai, (const uint2*)p_au,
                                     p_rp_u, p_cols_u, p_rp_i, p_cols_i,
                                     p_nu_is, p_ni_is,
                                     (uint2*)p_cu, (uint2*)p_ci);
        }
    }

    // ---- fused final sum ----
    final_sum<<<ALL_BLKS, TB>>>((const float4*)user_emb, (const float4*)item_emb,
                                p_nu_sq, p_ni_sq,
                                (const uint2*)p_ou1, (const uint2*)p_ou2, (const uint2*)p_cu,
                                (const uint2*)p_oi1, (const uint2*)p_oi2, (const uint2*)p_ci,
                                (float4*)out);
}

// round 8
// speedup vs baseline: 1.6633x; 1.6633x over previous
#include <cuda_runtime.h>
#include <cuda_fp16.h>

#define NUSER 100000
#define NITEM 50000
#define NEDGE 2000000
#define DIM   64
#define NLAYERS 3
#define SB    1024

// ---------------- scratch (device globals) ----------------
__device__ __half g_pu[NUSER * DIM];   // pre-scaled user operand (d_u^-1/2 * user_e)
__device__ __half g_pi[NITEM * DIM];   // pre-scaled item operand (d_i^-1/2 * item_e)
__device__ __half g_au[NUSER * DIM];   // phase-A out, user rows (d_u^-1 * R(pi))
__device__ __half g_ai[NITEM * DIM];   // phase-A out, item rows (d_i^-1 * RT(pu))
__device__ int    g_cnt_u[NUSER];
__device__ int    g_cnt_i[NITEM];
__device__ int    g_rowptr_u[NUSER + 1];
__device__ int    g_rowptr_i[NITEM + 1];
__device__ int    g_cur_u[NUSER];
__device__ int    g_cur_i[NITEM];
__device__ int    g_cols_u[NEDGE];
__device__ int    g_cols_i[NEDGE];
__device__ int    g_bsums_u[128];
__device__ int    g_bsums_i[128];
__device__ float  g_nu_inv[NUSER];
__device__ float  g_nu_is [NUSER];
__device__ float  g_ni_inv[NITEM];
__device__ float  g_ni_is [NITEM];

// ---------------- helpers ----------------
__device__ __forceinline__ uint2 pack4h(float4 v) {
    __half2 a = __floats2half2_rn(v.x, v.y);
    __half2 b = __floats2half2_rn(v.z, v.w);
    uint2 r;
    r.x = *reinterpret_cast<unsigned*>(&a);
    r.y = *reinterpret_cast<unsigned*>(&b);
    return r;
}

// gather-add over one CSR row: 16 lanes per row, 8B (4 halves) per lane.
// fp32 accumulation; moderate unroll (MLP_p1 ~ 4 avoids cross-CTA L1tex spread).
__device__ __forceinline__ float4 gather_row(const uint2* __restrict__ src,
                                             const int*   __restrict__ cols,
                                             int beg, int end, int c, unsigned hmask) {
    float4 acc = make_float4(0.f, 0.f, 0.f, 0.f);
    for (int base = beg; base < end; base += 16) {
        int myi = base + c;
        int mycol = (myi < end) ? __ldg(cols + myi) : 0;
        int cnt = min(16, end - base);
        #pragma unroll 4
        for (int j = 0; j < cnt; ++j) {
            int col = __shfl_sync(hmask, mycol, j, 16);
            uint2 v = __ldg(src + col * 16 + c);
            __half2 h0 = *reinterpret_cast<__half2*>(&v.x);
            __half2 h1 = *reinterpret_cast<__half2*>(&v.y);
            float2 f0 = __half22float2(h0);
            float2 f1 = __half22float2(h1);
            acc.x += f0.x; acc.y += f0.y; acc.z += f1.x; acc.w += f1.y;
        }
    }
    return acc;
}

// ---------------- CSR build ----------------
__global__ void hist_degrees(const int* __restrict__ u_idx,
                             const int* __restrict__ i_idx,
                             int* __restrict__ cnt_u, int* __restrict__ cnt_i) {
    int t = blockIdx.x * blockDim.x + threadIdx.x;
    if (t >= NEDGE) return;
    atomicAdd(cnt_u + __ldg(u_idx + t), 1);
    atomicAdd(cnt_i + __ldg(i_idx + t), 1);
}

__global__ void scan_block(const int* __restrict__ in, int* __restrict__ out,
                           int* __restrict__ bsums, int n) {
    __shared__ int sh[SB];
    int gid = blockIdx.x * SB + threadIdx.x;
    int v = (gid < n) ? in[gid] : 0;
    sh[threadIdx.x] = v;
    __syncthreads();
    for (int off = 1; off < SB; off <<= 1) {
        int t = (threadIdx.x >= off) ? sh[threadIdx.x - off] : 0;
        __syncthreads();
        sh[threadIdx.x] += t;
        __syncthreads();
    }
    if (gid < n) out[gid] = sh[threadIdx.x] - v;      // exclusive
    if (threadIdx.x == SB - 1) bsums[blockIdx.x] = sh[SB - 1];
}

__global__ void scan_small(int* __restrict__ data, int n) {
    __shared__ int sh[128];
    int v = (threadIdx.x < n) ? data[threadIdx.x] : 0;
    sh[threadIdx.x] = v;
    __syncthreads();
    for (int off = 1; off < 128; off <<= 1) {
        int t = (threadIdx.x >= off) ? sh[threadIdx.x - off] : 0;
        __syncthreads();
        sh[threadIdx.x] += t;
        __syncthreads();
    }
    if (threadIdx.x < n) data[threadIdx.x] = sh[threadIdx.x] - v;
}

// adds block offsets and also writes cur[] (eliminates 2 memcpy nodes vs R3)
__global__ void add_offsets(int* __restrict__ out, int* __restrict__ cur,
                            const int* __restrict__ bsums, int n) {
    int gid = blockIdx.x * SB + threadIdx.x;
    if (gid < n) {
        int v = out[gid] + bsums[blockIdx.x];
        out[gid] = v;
        cur[gid] = v;
    }
    if (gid == 0) out[n] = NEDGE;
}

__global__ void fill_csr(const int* __restrict__ u_idx, const int* __restrict__ i_idx,
                         int* __restrict__ cur_u, int* __restrict__ cur_i,
                         int* __restrict__ cols_u, int* __restrict__ cols_i) {
    int e = blockIdx.x * blockDim.x + threadIdx.x;
    if (e >= NEDGE) return;
    int u = __ldg(u_idx + e);
    int i = __ldg(i_idx + e);
    cols_u[atomicAdd(cur_u + u, 1)] = i;
    cols_i[atomicAdd(cur_i + i, 1)] = u;
}

__global__ void compute_norms(const int* __restrict__ cnt,
                              float* __restrict__ inv, float* __restrict__ invsqrt, int n) {
    int t = blockIdx.x * blockDim.x + threadIdx.x;
    if (t >= n) return;
    float d = (float)cnt[t];
    d = (d == 0.0f) ? 1.0f : d;
    inv[t]     = 1.0f / d;
    invsqrt[t] = rsqrtf(d);
}

// ---------------- prescale: P = d^-1/2 * emb  (fp32 -> fp16) ----------------
__global__ void prescale(const float4* __restrict__ ue, const float4* __restrict__ ie,
                         const float* __restrict__ nu_is, const float* __restrict__ ni_is,
                         uint2* __restrict__ pu, uint2* __restrict__ pi) {
    int t = blockIdx.x * blockDim.x + threadIdx.x;
    if (t >= (NUSER + NITEM) * 16) return;
    if (t < NUSER * 16) {
        float s = __ldg(nu_is + (t >> 4));
        float4 v = __ldg(ue + t);
        v.x *= s; v.y *= s; v.z *= s; v.w *= s;
        pu[t] = pack4h(v);
    } else {
        int tt = t - NUSER * 16;
        float s = __ldg(ni_is + (tt >> 4));
        float4 v = __ldg(ie + tt);
        v.x *= s; v.y *= s; v.z *= s; v.w *= s;
        pi[tt] = pack4h(v);
    }
}

// ---------------- phase A: ai = d_i^-1 * RT(pu);  au = d_u^-1 * R(pi) ----------------
__global__ void __launch_bounds__(256)
phaseA(const uint2* __restrict__ pu, const uint2* __restrict__ pi,
       const int* __restrict__ rp_i, const int* __restrict__ cols_i,
       const int* __restrict__ rp_u, const int* __restrict__ cols_u,
       const float* __restrict__ ni_inv, const float* __restrict__ nu_inv,
       uint2* __restrict__ ai, uint2* __restrict__ au) {
    int t = blockIdx.x * blockDim.x + threadIdx.x;
    int r = t >> 4;
    if (r >= NITEM + NUSER) return;
    int c = t & 15;
    unsigned hmask = 0xFFFFu << (threadIdx.x & 16);
    if (r < NITEM) {
        float4 acc = gather_row(pu, cols_i, __ldg(rp_i + r), __ldg(rp_i + r + 1), c, hmask);
        float s = __ldg(ni_inv + r);
        acc.x *= s; acc.y *= s; acc.z *= s; acc.w *= s;
        ai[r * 16 + c] = pack4h(acc);
    } else {
        int u = r - NITEM;
        float4 acc = gather_row(pi, cols_u, __ldg(rp_u + u), __ldg(rp_u + u + 1), c, hmask);
        float s = __ldg(nu_inv + u);
        acc.x *= s; acc.y *= s; acc.z *= s; acc.w *= s;
        au[u * 16 + c] = pack4h(acc);
    }
}

// ---------------- phase B: S_u = R(ai), S_i = RT(au); sums + next operands ----------------
__global__ void __launch_bounds__(256)
phaseB(const uint2* __restrict__ ai, const uint2* __restrict__ au,
       const int* __restrict__ rp_u, const int* __restrict__ cols_u,
       const int* __restrict__ rp_i, const int* __restrict__ cols_i,
       const float* __restrict__ nu_is, const float* __restrict__ nu_inv,
       const float* __restrict__ ni_is, const float* __restrict__ ni_inv,
       const float4* __restrict__ emb_u, const float4* __restrict__ emb_i,
       float4* __restrict__ sum_u, float4* __restrict__ sum_i,
       uint2* __restrict__ pu, uint2* __restrict__ pi,
       int layer0, int last) {
    int t = blockIdx.x * blockDim.x + threadIdx.x;
    int r = t >> 4;
    if (r >= NITEM + NUSER) return;
    int c = t & 15;
    unsigned hmask = 0xFFFFu << (threadIdx.x & 16);
    const float k = 1.0f / (NLAYERS + 1);
    if (r < NUSER) {
        int idx = r * 16 + c;
        float4 S = gather_row(ai, cols_u, __ldg(rp_u + r), __ldg(rp_u + r + 1), c, hmask);
        float sis = __ldg(nu_is + r);
        float4 base = layer0 ? __ldg(emb_u + idx) : sum_u[idx];
        float4 ns;
        ns.x = base.x + sis * S.x; ns.y = base.y + sis * S.y;
        ns.z = base.z + sis * S.z; ns.w = base.w + sis * S.w;
        if (last) { ns.x *= k; ns.y *= k; ns.z *= k; ns.w *= k; }
        sum_u[idx] = ns;
        if (!last) {
            float si = __ldg(nu_inv + r);
            float4 p; p.x = si * S.x; p.y = si * S.y; p.z = si * S.z; p.w = si * S.w;
            pu[idx] = pack4h(p);
        }
    } else {
        int i = r - NUSER;
        int idx = i * 16 + c;
        float4 S = gather_row(au, cols_i, __ldg(rp_i + i), __ldg(rp_i + i + 1), c, hmask);
        float sis = __ldg(ni_is + i);
        float4 base = layer0 ? __ldg(emb_i + idx) : sum_i[idx];
        float4 ns;
        ns.x = base.x + sis * S.x; ns.y = base.y + sis * S.y;
        ns.z = base.z + sis * S.z; ns.w = base.w + sis * S.w;
        if (last) { ns.x *= k; ns.y *= k; ns.z *= k; ns.w *= k; }
        sum_i[idx] = ns;
        if (!last) {
            float si = __ldg(ni_inv + i);
            float4 p; p.x = si * S.x; p.y = si * S.y; p.z = si * S.z; p.w = si * S.w;
            pi[idx] = pack4h(p);
        }
    }
}

// ---------------- launch ----------------
extern "C" void kernel_launch(void* const* d_in, const int* in_sizes, int n_in,
                              void* d_out, int out_size) {
    const float* user_emb = (const float*)d_in[0];
    const float* item_emb = (const float*)d_in[1];
    const int*   u_idx    = (const int*)d_in[2];
    const int*   i_idx    = (const int*)d_in[3];
    float* out = (float*)d_out;
    float* sum_u = out;
    float* sum_i = out + NUSER * DIM;

    __half *p_pu, *p_pi, *p_au, *p_ai;
    float *p_nu_inv, *p_nu_is, *p_ni_inv, *p_ni_is;
    int *p_cnt_u, *p_cnt_i, *p_rp_u, *p_rp_i, *p_cur_u, *p_cur_i;
    int *p_cols_u, *p_cols_i, *p_bs_u, *p_bs_i;
    cudaGetSymbolAddress((void**)&p_pu, g_pu);
    cudaGetSymbolAddress((void**)&p_pi, g_pi);
    cudaGetSymbolAddress((void**)&p_au, g_au);
    cudaGetSymbolAddress((void**)&p_ai, g_ai);
    cudaGetSymbolAddress((void**)&p_nu_inv, g_nu_inv);
    cudaGetSymbolAddress((void**)&p_nu_is,  g_nu_is);
    cudaGetSymbolAddress((void**)&p_ni_inv, g_ni_inv);
    cudaGetSymbolAddress((void**)&p_ni_is,  g_ni_is);
    cudaGetSymbolAddress((void**)&p_cnt_u,  g_cnt_u);
    cudaGetSymbolAddress((void**)&p_cnt_i,  g_cnt_i);
    cudaGetSymbolAddress((void**)&p_rp_u,   g_rowptr_u);
    cudaGetSymbolAddress((void**)&p_rp_i,   g_rowptr_i);
    cudaGetSymbolAddress((void**)&p_cur_u,  g_cur_u);
    cudaGetSymbolAddress((void**)&p_cur_i,  g_cur_i);
    cudaGetSymbolAddress((void**)&p_cols_u, g_cols_u);
    cudaGetSymbolAddress((void**)&p_cols_i, g_cols_i);
    cudaGetSymbolAddress((void**)&p_bs_u,   g_bsums_u);
    cudaGetSymbolAddress((void**)&p_bs_i,   g_bsums_i);

    const int TB = 256;
    const int EDGE_BLKS = (NEDGE + TB - 1) / TB;
    const int SCAN_BU = (NUSER + SB - 1) / SB;   // 98
    const int SCAN_BI = (NITEM + SB - 1) / SB;   // 49
    const int ALL_BLKS = ((NUSER + NITEM) * 16 + TB - 1) / TB;

    // ---- CSR build + norms (proven round-3 chain; memcpys folded into add_offsets) ----
    cudaMemsetAsync(p_cnt_u, 0, NUSER * sizeof(int), 0);
    cudaMemsetAsync(p_cnt_i, 0, NITEM * sizeof(int), 0);
    hist_degrees<<<EDGE_BLKS, TB>>>(u_idx, i_idx, p_cnt_u, p_cnt_i);
    compute_norms<<<(NUSER + TB - 1) / TB, TB>>>(p_cnt_u, p_nu_inv, p_nu_is, NUSER);
    compute_norms<<<(NITEM + TB - 1) / TB, TB>>>(p_cnt_i, p_ni_inv, p_ni_is, NITEM);
    scan_block<<<SCAN_BU, SB>>>(p_cnt_u, p_rp_u, p_bs_u, NUSER);
    scan_small<<<1, 128>>>(p_bs_u, SCAN_BU);
    add_offsets<<<SCAN_BU, SB>>>(p_rp_u, p_cur_u, p_bs_u, NUSER);
    scan_block<<<SCAN_BI, SB>>>(p_cnt_i, p_rp_i, p_bs_i, NITEM);
    scan_small<<<1, 128>>>(p_bs_i, SCAN_BI);
    add_offsets<<<SCAN_BI, SB>>>(p_rp_i, p_cur_i, p_bs_i, NITEM);
    fill_csr<<<EDGE_BLKS, TB>>>(u_idx, i_idx, p_cur_u, p_cur_i, p_cols_u, p_cols_i);

    // ---- initial pre-scaled operands ----
    prescale<<<ALL_BLKS, TB>>>((const float4*)user_emb, (const float4*)item_emb,
                               p_nu_is, p_ni_is, (uint2*)p_pu, (uint2*)p_pi);

    // ---- layers ----
    for (int layer = 0; layer < NLAYERS; ++layer) {
        phaseA<<<ALL_BLKS, TB>>>((const uint2*)p_pu, (const uint2*)p_pi,
                                 p_rp_i, p_cols_i, p_rp_u, p_cols_u,
                                 p_ni_inv, p_nu_inv, (uint2*)p_ai, (uint2*)p_au);
        phaseB<<<ALL_BLKS, TB>>>((const uint2*)p_ai, (const uint2*)p_au,
                                 p_rp_u, p_cols_u, p_rp_i, p_cols_i,
                                 p_nu_is, p_nu_inv, p_ni_is, p_ni_inv,
                                 (const float4*)user_emb, (const float4*)item_emb,
                                 (float4*)sum_u, (float4*)sum_i,
                                 (uint2*)p_pu, (uint2*)p_pi,
                                 layer == 0 ? 1 : 0, layer == NLAYERS - 1 ? 1 : 0);
    }
}